// round 3
// baseline (speedup 1.0000x reference)
#include <cuda_runtime.h>
#include <cuda_bf16.h>

namespace {

constexpr int Bn  = 512;
constexpr int DKn = 256;
constexpr int DVn = 256;
constexpr int Pn  = 2048;
constexpr float SCALEf = 1.0f / 16.0f;   // 1/sqrt(256)

__device__ __forceinline__ float4 ldcs4(const float* p) {
    return __ldcs(reinterpret_cast<const float4*>(p));
}

__global__ void __launch_bounds__(256, 3)
attn_kernel(const float* __restrict__ Q,
            const float* __restrict__ K,
            const float* __restrict__ V,
            const int*   __restrict__ mask,
            float*       __restrict__ out)
{
    __shared__ float sQ[DKn];
    __shared__ float sW[Pn];
    __shared__ float sRed[8];

    const int b    = blockIdx.x;
    const int t    = threadIdx.x;
    const int lane = t & 31;
    const int warp = t >> 5;

    // ---- load Q row into smem ----
    sQ[t] = Q[(size_t)b * DKn + t];
    __syncthreads();

    // ---- Phase 1: energy[p] = sum_d Q[d] * K[d][p] ----
    // Each thread owns 8 p-slots: [4t, 4t+4) and [1024+4t, 1024+4t+4).
    const int pA = 4 * t;
    const int pB = (Pn / 2) + 4 * t;

    const float* kpA = K + (size_t)b * DKn * Pn + pA;
    const float* kpB = K + (size_t)b * DKn * Pn + pB;

    float4 aA = make_float4(0.f, 0.f, 0.f, 0.f);
    float4 aB = make_float4(0.f, 0.f, 0.f, 0.f);

    #pragma unroll 4
    for (int d = 0; d < DKn; ++d) {
        const float q = sQ[d];
        const float4 kA = ldcs4(kpA);
        const float4 kB = ldcs4(kpB);
        kpA += Pn;
        kpB += Pn;
        aA.x = fmaf(q, kA.x, aA.x);
        aA.y = fmaf(q, kA.y, aA.y);
        aA.z = fmaf(q, kA.z, aA.z);
        aA.w = fmaf(q, kA.w, aA.w);
        aB.x = fmaf(q, kB.x, aB.x);
        aB.y = fmaf(q, kB.y, aB.y);
        aB.z = fmaf(q, kB.z, aB.z);
        aB.w = fmaf(q, kB.w, aB.w);
    }

    // ---- multiplicative mask + scale (masked -> exactly 0.0, NOT -inf) ----
    const int4 mA = __ldcs(reinterpret_cast<const int4*>(mask + (size_t)b * Pn + pA));
    const int4 mB = __ldcs(reinterpret_cast<const int4*>(mask + (size_t)b * Pn + pB));

    float e[8];
    e[0] = mA.x ? aA.x * SCALEf : 0.f;
    e[1] = mA.y ? aA.y * SCALEf : 0.f;
    e[2] = mA.z ? aA.z * SCALEf : 0.f;
    e[3] = mA.w ? aA.w * SCALEf : 0.f;
    e[4] = mB.x ? aB.x * SCALEf : 0.f;
    e[5] = mB.y ? aB.y * SCALEf : 0.f;
    e[6] = mB.z ? aB.z * SCALEf : 0.f;
    e[7] = mB.w ? aB.w * SCALEf : 0.f;

    // ---- Phase 2: softmax over 2048 ----
    float lmax = e[0];
    #pragma unroll
    for (int i = 1; i < 8; ++i) lmax = fmaxf(lmax, e[i]);

    float v = lmax;
    #pragma unroll
    for (int o = 16; o; o >>= 1) v = fmaxf(v, __shfl_xor_sync(0xffffffffu, v, o));
    if (lane == 0) sRed[warp] = v;
    __syncthreads();
    float gmax = sRed[0];
    #pragma unroll
    for (int i = 1; i < 8; ++i) gmax = fmaxf(gmax, sRed[i]);
    __syncthreads();   // sRed about to be reused for sum

    float w[8];
    float lsum = 0.f;
    #pragma unroll
    for (int i = 0; i < 8; ++i) {
        w[i] = __expf(e[i] - gmax);
        lsum += w[i];
    }
    // un-normalized weights into smem
    *reinterpret_cast<float4*>(&sW[pA]) = make_float4(w[0], w[1], w[2], w[3]);
    *reinterpret_cast<float4*>(&sW[pB]) = make_float4(w[4], w[5], w[6], w[7]);

    v = lsum;
    #pragma unroll
    for (int o = 16; o; o >>= 1) v += __shfl_xor_sync(0xffffffffu, v, o);
    if (lane == 0) sRed[warp] = v;
    __syncthreads();   // also publishes sW
    float gsum = sRed[0];
    #pragma unroll
    for (int i = 1; i < 8; ++i) gsum += sRed[i];
    const float inv = 1.0f / gsum;

    // ---- Phase 3: out[v] = inv * sum_p w[p] * V[v][p] ----
    const float* __restrict__ Vb = V + (size_t)b * DVn * Pn;
    #pragma unroll 1
    for (int vr = warp; vr < DVn; vr += 8) {
        const float* __restrict__ Vr = Vb + (size_t)vr * Pn + lane * 4;
        float4 acc = make_float4(0.f, 0.f, 0.f, 0.f);
        #pragma unroll
        for (int i = 0; i < Pn / 128; ++i) {       // 16 iters
            const float4 vv = ldcs4(Vr + i * 128);
            const float4 ww = *reinterpret_cast<const float4*>(&sW[i * 128 + lane * 4]);
            acc.x = fmaf(ww.x, vv.x, acc.x);
            acc.y = fmaf(ww.y, vv.y, acc.y);
            acc.z = fmaf(ww.z, vv.z, acc.z);
            acc.w = fmaf(ww.w, vv.w, acc.w);
        }
        float s = (acc.x + acc.y) + (acc.z + acc.w);
        #pragma unroll
        for (int o = 16; o; o >>= 1) s += __shfl_xor_sync(0xffffffffu, s, o);
        if (lane == 0) out[(size_t)b * DVn + vr] = s * inv;
    }
}

} // namespace

extern "C" void kernel_launch(void* const* d_in, const int* in_sizes, int n_in,
                              void* d_out, int out_size)
{
    const float* Q    = (const float*)d_in[0];
    const float* K    = (const float*)d_in[1];
    const float* V    = (const float*)d_in[2];
    const int*   mask = (const int*)d_in[3];
    float*       out  = (float*)d_out;

    attn_kernel<<<Bn, 256>>>(Q, K, V, mask, out);
}

// round 4
// speedup vs baseline: 1.3066x; 1.3066x over previous
#include <cuda_runtime.h>
#include <cuda_bf16.h>

namespace {

constexpr int Bn  = 512;
constexpr int DKn = 256;
constexpr int DVn = 256;
constexpr int Pn  = 2048;
constexpr float SCALEf = 1.0f / 16.0f;   // 1/sqrt(256)

__global__ void __launch_bounds__(256, 2)
attn_kernel(const float* __restrict__ Q,
            const float* __restrict__ K,
            const float* __restrict__ V,
            const int*   __restrict__ mask,
            float*       __restrict__ out)
{
    __shared__ float sQ[DKn];
    __shared__ float sW[Pn];
    __shared__ float sRed[8];

    const int b    = blockIdx.x;
    const int t    = threadIdx.x;
    const int lane = t & 31;
    const int warp = t >> 5;

    // ---- load Q row into smem ----
    sQ[t] = Q[(size_t)b * DKn + t];
    __syncthreads();

    // ---- Phase 1: energy[p] = sum_d Q[d] * K[d][p] ----
    // Each thread owns 8 p-slots: [4t, 4t+4) and [1024+4t, 1024+4t+4).
    const float* __restrict__ Kb = K + (size_t)b * DKn * Pn;
    const int pA = 4 * t;
    const int pB = (Pn / 2) + 4 * t;

    float4 aA = make_float4(0.f, 0.f, 0.f, 0.f);
    float4 aB = make_float4(0.f, 0.f, 0.f, 0.f);

    // d-chunks of 8: issue all 16 float4 loads up front (high MLP), then FMA.
    #pragma unroll 1
    for (int d0 = 0; d0 < DKn; d0 += 8) {
        float4 kA[8], kB[8];
        #pragma unroll
        for (int i = 0; i < 8; ++i) {
            const float* base = Kb + (size_t)(d0 + i) * Pn;
            kA[i] = *reinterpret_cast<const float4*>(base + pA);
            kB[i] = *reinterpret_cast<const float4*>(base + pB);
        }
        #pragma unroll
        for (int i = 0; i < 8; ++i) {
            const float q = sQ[d0 + i];
            aA.x = fmaf(q, kA[i].x, aA.x);
            aA.y = fmaf(q, kA[i].y, aA.y);
            aA.z = fmaf(q, kA[i].z, aA.z);
            aA.w = fmaf(q, kA[i].w, aA.w);
            aB.x = fmaf(q, kB[i].x, aB.x);
            aB.y = fmaf(q, kB[i].y, aB.y);
            aB.z = fmaf(q, kB[i].z, aB.z);
            aB.w = fmaf(q, kB[i].w, aB.w);
        }
    }

    // ---- multiplicative mask + scale (masked -> exactly 0.0, NOT -inf) ----
    const int4 mA = *reinterpret_cast<const int4*>(mask + (size_t)b * Pn + pA);
    const int4 mB = *reinterpret_cast<const int4*>(mask + (size_t)b * Pn + pB);

    float e[8];
    e[0] = mA.x ? aA.x * SCALEf : 0.f;
    e[1] = mA.y ? aA.y * SCALEf : 0.f;
    e[2] = mA.z ? aA.z * SCALEf : 0.f;
    e[3] = mA.w ? aA.w * SCALEf : 0.f;
    e[4] = mB.x ? aB.x * SCALEf : 0.f;
    e[5] = mB.y ? aB.y * SCALEf : 0.f;
    e[6] = mB.z ? aB.z * SCALEf : 0.f;
    e[7] = mB.w ? aB.w * SCALEf : 0.f;

    // ---- Phase 2: softmax over 2048 ----
    float lmax = e[0];
    #pragma unroll
    for (int i = 1; i < 8; ++i) lmax = fmaxf(lmax, e[i]);

    float v = lmax;
    #pragma unroll
    for (int o = 16; o; o >>= 1) v = fmaxf(v, __shfl_xor_sync(0xffffffffu, v, o));
    if (lane == 0) sRed[warp] = v;
    __syncthreads();
    float gmax = sRed[0];
    #pragma unroll
    for (int i = 1; i < 8; ++i) gmax = fmaxf(gmax, sRed[i]);
    __syncthreads();   // sRed about to be reused for sum

    float w[8];
    float lsum = 0.f;
    #pragma unroll
    for (int i = 0; i < 8; ++i) {
        w[i] = __expf(e[i] - gmax);
        lsum += w[i];
    }
    // un-normalized weights into smem
    *reinterpret_cast<float4*>(&sW[pA]) = make_float4(w[0], w[1], w[2], w[3]);
    *reinterpret_cast<float4*>(&sW[pB]) = make_float4(w[4], w[5], w[6], w[7]);

    v = lsum;
    #pragma unroll
    for (int o = 16; o; o >>= 1) v += __shfl_xor_sync(0xffffffffu, v, o);
    if (lane == 0) sRed[warp] = v;
    __syncthreads();   // also publishes sW
    float gsum = sRed[0];
    #pragma unroll
    for (int i = 1; i < 8; ++i) gsum += sRed[i];
    const float inv = 1.0f / gsum;

    // ---- Phase 3: out[v] = inv * sum_p w[p] * V[v][p] ----
    const float* __restrict__ Vb = V + (size_t)b * DVn * Pn;
    #pragma unroll 1
    for (int vr = warp; vr < DVn; vr += 8) {
        const float* __restrict__ Vr = Vb + (size_t)vr * Pn;
        float4 acc = make_float4(0.f, 0.f, 0.f, 0.f);
        #pragma unroll
        for (int i = 0; i < Pn / 128; ++i) {       // 16 iters
            const int p = i * 128 + lane * 4;
            const float4 vv = *reinterpret_cast<const float4*>(Vr + p);
            const float4 ww = *reinterpret_cast<const float4*>(&sW[p]);
            acc.x = fmaf(ww.x, vv.x, acc.x);
            acc.y = fmaf(ww.y, vv.y, acc.y);
            acc.z = fmaf(ww.z, vv.z, acc.z);
            acc.w = fmaf(ww.w, vv.w, acc.w);
        }
        float s = (acc.x + acc.y) + (acc.z + acc.w);
        #pragma unroll
        for (int o = 16; o; o >>= 1) s += __shfl_xor_sync(0xffffffffu, s, o);
        if (lane == 0) out[(size_t)b * DVn + vr] = s * inv;
    }
}

} // namespace

extern "C" void kernel_launch(void* const* d_in, const int* in_sizes, int n_in,
                              void* d_out, int out_size)
{
    const float* Q    = (const float*)d_in[0];
    const float* K    = (const float*)d_in[1];
    const float* V    = (const float*)d_in[2];
    const int*   mask = (const int*)d_in[3];
    float*       out  = (float*)d_out;

    attn_kernel<<<Bn, 256>>>(Q, K, V, mask, out);
}